// round 3
// baseline (speedup 1.0000x reference)
#include <cuda_runtime.h>
#include <cstddef>

// Problem constants
// B=32, N=4096, D_U=64, D=128, H=2, DH=64
#define BATCH 32
#define SEQN 4096
#define DU 64
#define DMODEL 128
#define TILES 32            // SEQN / 128
#define TM 128              // rows per tile
#define US 68               // padded row stride for u tile (floats)
#define ZS 132              // padded row stride for z tile (floats)

typedef unsigned long long ULL;

// ---------------- scratch (no allocations allowed) ----------------
__device__ float g_a[2 * 128];                 // a_h[c]
__device__ float g_c[2];                       // c_h
__device__ float g_mp[TILES * BATCH * 256];    // per-tile partial m  [tile][b][h*128+c]
__device__ float g_Sp[TILES * BATCH * 2];      // per-tile partial S

// ---------------- helpers ----------------
__device__ __forceinline__ ULL pk2(float lo, float hi) {
    ULL r;
    asm("mov.b64 %0, {%1,%2};" : "=l"(r) : "f"(lo), "f"(hi));
    return r;
}
__device__ __forceinline__ void upk2(ULL v, float& lo, float& hi) {
    asm("mov.b64 {%0,%1}, %2;" : "=f"(lo), "=f"(hi) : "l"(v));
}
__device__ __forceinline__ void ffma2(ULL& d, ULL a, ULL b) {
    asm("fma.rn.f32x2 %0, %1, %2, %0;" : "+l"(d) : "l"(a), "l"(b));
}
// jax.nn.gelu default (approximate=True): 0.5x(1+tanh(sqrt(2/pi)(x+0.044715x^3)))
__device__ __forceinline__ float gelu_f(float x) {
    float x2 = x * x;
    float inner = fmaf(0.044715f * x2, x, x);
    float arg = 0.7978845608028654f * inner;
    float t;
    asm("tanh.approx.f32 %0, %1;" : "=f"(t) : "f"(arg));
    return 0.5f * x * (1.0f + t);
}

// ---------------- prep: q = embed@Wq+bq ; a_h = Wk_h @ q_h ; c_h = q_h . bk_h ----
__global__ void prep_kernel(const float* __restrict__ embed,
                            const float* __restrict__ Wq, const float* __restrict__ bq,
                            const float* __restrict__ Wk, const float* __restrict__ bk) {
    __shared__ float sq[128];
    int t = threadIdx.x;  // 128 threads
    float q = bq[t];
    #pragma unroll 4
    for (int c = 0; c < 128; c++) q = fmaf(embed[c], Wq[c * 128 + t], q);
    sq[t] = q;
    __syncthreads();
    // t plays role of c (row of Wk)
    float a0 = 0.f, a1 = 0.f;
    #pragma unroll 4
    for (int d = 0; d < 64; d++) {
        a0 = fmaf(Wk[t * 128 + d], sq[d], a0);
        a1 = fmaf(Wk[t * 128 + 64 + d], sq[64 + d], a1);
    }
    g_a[t] = a0;
    g_a[128 + t] = a1;
    if (t < 2) {
        float c0 = 0.f;
        #pragma unroll 4
        for (int d = 0; d < 64; d++) c0 = fmaf(bk[t * 64 + d], sq[t * 64 + d], c0);
        g_c[t] = c0;
    }
}

// ---------------- main: MLP + score + per-tile reductions ----------------
// grid (32 tiles, 32 batches), 256 threads.
// Thread (ty = tid/16, tx = tid%16): rows {ty + 16*i, i=0..7},
// cols {4tx..4tx+3} U {64+4tx..64+4tx+3}  (f32x2 pairs along cols).
__global__ void __launch_bounds__(256, 1)
main_kernel(const float* __restrict__ u,
            const float* __restrict__ W1, const float* __restrict__ b1,
            const float* __restrict__ W2, const float* __restrict__ b2) {
    extern __shared__ float smem[];
    // layout (floats):
    //   [0 .. 8704)        sU   (128 x 68)     | overlapped later by sW2 (128x128=16384)
    //   [8704 .. 16896)    sW1  (64 x 128)     |
    //   [16896 .. 33792)   sZ   (128 x 132)
    //   [33792 .. 34048)   sS   (128 x 2)
    //   [34048 .. 34304)   sA   (2 x 128)
    float* sU = smem;
    float* sW1 = smem + 8704;
    float* sW2 = smem;          // reuses region A after GEMM1
    float* sZ = smem + 16896;
    float* sS = smem + 33792;
    float* sA = smem + 34048;

    const int tid = threadIdx.x;
    const int tx = tid & 15;
    const int ty = tid >> 4;
    const int tile = blockIdx.x;
    const int b = blockIdx.y;

    // ---- phase 0: load u tile (padded-transposed-free, row stride 68) + W1 + a ----
    {
        const float4* uT = (const float4*)(u + ((size_t)b * SEQN + (size_t)tile * TM) * DU);
        float4* sUv = (float4*)sU;
        #pragma unroll
        for (int i = 0; i < 8; i++) {
            int idx = tid + i * 256;        // 0..2047
            int row = idx >> 4, q = idx & 15;
            sUv[row * 17 + q] = uT[idx];
        }
        float4* sW1v = (float4*)sW1;
        const float4* W1v = (const float4*)W1;
        #pragma unroll
        for (int i = 0; i < 8; i++) sW1v[tid + i * 256] = W1v[tid + i * 256];
        sA[tid] = g_a[tid];
    }
    __syncthreads();

    ULL acc[8][4];

    // ---- GEMM1: z1 = gelu(u @ W1 + b1) ----
    #pragma unroll
    for (int i = 0; i < 8; i++)
        #pragma unroll
        for (int j = 0; j < 4; j++) acc[i][j] = 0ULL;

    #pragma unroll 2
    for (int k = 0; k < DU; k++) {
        ULL a2[8];
        #pragma unroll
        for (int i = 0; i < 8; i++) {
            float av = sU[(ty + 16 * i) * US + k];
            a2[i] = pk2(av, av);
        }
        const ulonglong2* wr = (const ulonglong2*)(sW1 + k * 128);
        ulonglong2 w0 = wr[tx];
        ulonglong2 w1 = wr[16 + tx];
        ULL bb0 = w0.x, bb1 = w0.y, bb2 = w1.x, bb3 = w1.y;
        #pragma unroll
        for (int i = 0; i < 8; i++) {
            ffma2(acc[i][0], a2[i], bb0);
            ffma2(acc[i][1], a2[i], bb1);
            ffma2(acc[i][2], a2[i], bb2);
            ffma2(acc[i][3], a2[i], bb3);
        }
    }
    // bias + gelu + store z1 -> sZ
    {
        float4 bA = ((const float4*)b1)[tx];
        float4 bB = ((const float4*)b1)[16 + tx];
        #pragma unroll
        for (int i = 0; i < 8; i++) {
            int row = ty + 16 * i;
            float x0, x1, x2, x3, y0, y1, y2, y3;
            upk2(acc[i][0], x0, x1);
            upk2(acc[i][1], x2, x3);
            upk2(acc[i][2], y0, y1);
            upk2(acc[i][3], y2, y3);
            float4 o0 = make_float4(gelu_f(x0 + bA.x), gelu_f(x1 + bA.y),
                                    gelu_f(x2 + bA.z), gelu_f(x3 + bA.w));
            float4 o1 = make_float4(gelu_f(y0 + bB.x), gelu_f(y1 + bB.y),
                                    gelu_f(y2 + bB.z), gelu_f(y3 + bB.w));
            float4* zr = (float4*)(sZ + row * ZS);
            zr[tx] = o0;
            zr[16 + tx] = o1;
        }
    }
    __syncthreads();   // GEMM1 reads done, z1 fully in sZ

    // ---- load W2 into region A ----
    {
        float4* sW2v = (float4*)sW2;
        const float4* W2v = (const float4*)W2;
        #pragma unroll
        for (int i = 0; i < 16; i++) sW2v[tid + i * 256] = W2v[tid + i * 256];
    }
    __syncthreads();

    // ---- GEMM2: z2 = gelu(z1 @ W2 + b2) ----
    #pragma unroll
    for (int i = 0; i < 8; i++)
        #pragma unroll
        for (int j = 0; j < 4; j++) acc[i][j] = 0ULL;

    #pragma unroll 2
    for (int k = 0; k < DMODEL; k++) {
        ULL a2[8];
        #pragma unroll
        for (int i = 0; i < 8; i++) {
            float av = sZ[(ty + 16 * i) * ZS + k];
            a2[i] = pk2(av, av);
        }
        const ulonglong2* wr = (const ulonglong2*)(sW2 + k * 128);
        ulonglong2 w0 = wr[tx];
        ulonglong2 w1 = wr[16 + tx];
        ULL bb0 = w0.x, bb1 = w0.y, bb2 = w1.x, bb3 = w1.y;
        #pragma unroll
        for (int i = 0; i < 8; i++) {
            ffma2(acc[i][0], a2[i], bb0);
            ffma2(acc[i][1], a2[i], bb1);
            ffma2(acc[i][2], a2[i], bb2);
            ffma2(acc[i][3], a2[i], bb3);
        }
    }
    __syncthreads();   // everyone done READING sZ(z1) before overwrite with z2
    {
        float4 bA = ((const float4*)b2)[tx];
        float4 bB = ((const float4*)b2)[16 + tx];
        #pragma unroll
        for (int i = 0; i < 8; i++) {
            int row = ty + 16 * i;
            float x0, x1, x2, x3, y0, y1, y2, y3;
            upk2(acc[i][0], x0, x1);
            upk2(acc[i][1], x2, x3);
            upk2(acc[i][2], y0, y1);
            upk2(acc[i][3], y2, y3);
            float4 o0 = make_float4(gelu_f(x0 + bA.x), gelu_f(x1 + bA.y),
                                    gelu_f(x2 + bA.z), gelu_f(x3 + bA.w));
            float4 o1 = make_float4(gelu_f(y0 + bB.x), gelu_f(y1 + bB.y),
                                    gelu_f(y2 + bB.z), gelu_f(y3 + bB.w));
            float4* zr = (float4*)(sZ + row * ZS);
            zr[tx] = o0;
            zr[16 + tx] = o1;
        }
    }
    __syncthreads();

    // ---- phase 3: scores s[r][h] = c_h + a_h . z2[r] ----
    {
        int r = tid >> 1, h = tid & 1;
        const float4* ar = (const float4*)(sA + h * 128);
        const float4* zr = (const float4*)(sZ + r * ZS);
        float s = g_c[h];
        #pragma unroll 8
        for (int c = 0; c < 32; c++) {
            float4 zz = zr[c];
            float4 aa = ar[c];
            s = fmaf(zz.x, aa.x, s);
            s = fmaf(zz.y, aa.y, s);
            s = fmaf(zz.z, aa.z, s);
            s = fmaf(zz.w, aa.w, s);
        }
        sS[r * 2 + h] = s;
    }
    __syncthreads();

    // ---- phase 4: partial m_h[col] = sum_r s[r][h] * z2[r][col] ; partial S ----
    {
        int h = tid >> 7, col = tid & 127;
        float accm = 0.f;
        #pragma unroll 4
        for (int r = 0; r < TM; r++) accm = fmaf(sS[r * 2 + h], sZ[r * ZS + col], accm);
        g_mp[((size_t)(tile * BATCH + b)) * 256 + tid] = accm;
        if (tid < 2) {
            float S = 0.f;
            #pragma unroll 4
            for (int r = 0; r < TM; r++) S += sS[r * 2 + tid];
            g_Sp[(tile * BATCH + b) * 2 + tid] = S;
        }
    }
}

// ---------------- finish: reduce partials, V-proj, O-proj ----------------
__global__ void finish_kernel(const float* __restrict__ Wv, const float* __restrict__ bv,
                              const float* __restrict__ Wo, const float* __restrict__ bo,
                              float* __restrict__ out) {
    __shared__ float sm[256];
    __shared__ float sSs[2];
    __shared__ float sop[128];
    int b = blockIdx.x;
    int t = threadIdx.x;  // 128 threads
    float m0 = 0.f, m1 = 0.f;
    for (int tile = 0; tile < TILES; tile++) {
        const float* p = g_mp + ((size_t)(tile * BATCH + b)) * 256;
        m0 += p[t];
        m1 += p[128 + t];
    }
    sm[t] = m0;
    sm[128 + t] = m1;
    if (t < 2) {
        float S = 0.f;
        for (int tile = 0; tile < TILES; tile++) S += g_Sp[(tile * BATCH + b) * 2 + t];
        sSs[t] = S;
    }
    __syncthreads();
    int h = t >> 6;  // t = h*64 + e
    float acc = 0.f;
    #pragma unroll 4
    for (int d = 0; d < 128; d++) acc = fmaf(sm[h * 128 + d], Wv[d * 128 + t], acc);
    acc = (acc + sSs[h] * bv[t]) * (1.0f / (float)SEQN);
    sop[t] = acc;
    __syncthreads();
    float o = bo[t];
    #pragma unroll 4
    for (int j = 0; j < 128; j++) o = fmaf(sop[j], Wo[j * 128 + t], o);
    out[b * 128 + t] = o;
}

// ---------------- launch ----------------
extern "C" void kernel_launch(void* const* d_in, const int* in_sizes, int n_in,
                              void* d_out, int out_size) {
    const float* u     = (const float*)d_in[0];
    // d_in[1] = x, unused by the reference output
    const float* W1    = (const float*)d_in[2];
    const float* b1    = (const float*)d_in[3];
    const float* W2    = (const float*)d_in[4];
    const float* b2    = (const float*)d_in[5];
    const float* embed = (const float*)d_in[6];
    const float* Wq    = (const float*)d_in[7];
    const float* bq    = (const float*)d_in[8];
    const float* Wk    = (const float*)d_in[9];
    const float* bk    = (const float*)d_in[10];
    const float* Wv    = (const float*)d_in[11];
    const float* bv    = (const float*)d_in[12];
    const float* Wo    = (const float*)d_in[13];
    const float* bo    = (const float*)d_in[14];
    float* out = (float*)d_out;

    const int SMEM_BYTES = 34304 * (int)sizeof(float);  // 137216 B
    cudaFuncSetAttribute(main_kernel, cudaFuncAttributeMaxDynamicSharedMemorySize, SMEM_BYTES);

    prep_kernel<<<1, 128>>>(embed, Wq, bq, Wk, bk);
    main_kernel<<<dim3(TILES, BATCH), 256, SMEM_BYTES>>>(u, W1, b1, W2, b2);
    finish_kernel<<<BATCH, 128>>>(Wv, bv, Wo, bo, out);
}

// round 6
// speedup vs baseline: 1.5726x; 1.5726x over previous
#include <cuda_runtime.h>
#include <cuda_bf16.h>
#include <cstdint>
#include <cstddef>

// Problem constants: B=32, N=4096, D_U=64, D=128, H=2, DH=64
#define BATCH 32
#define SEQN 4096
#define TILES 32

typedef unsigned long long ULL;

// ---- arch-feature gate: tcgen05 only exists on 'a'/'f' suffixed targets ----
#if defined(__CUDA_ARCH__) && (__CUDA_ARCH__ >= 1000) && \
    (defined(__CUDA_ARCH_FEAT_SM103_ALL) || defined(__CUDA_ARCH_FEAT_SM100_ALL) || \
     defined(__CUDA_ARCH_SPECIFIC__) || defined(__CUDA_ARCH_FAMILY_SPECIFIC__))
#define TC_OK 1
#else
#define TC_OK 0
#endif

// ---------------- TMEM column layout (TC path) ----------------
#define T_A2HI 0
#define T_A2LO 64
#define T_D1   128
#define T_D2   256
#define TMEM_COLS 512

// ---------------- SMEM layout for TC path (bytes) ----------------
#define S_A1HI 0
#define S_A1LO 16384
#define S_B1HI 32768
#define S_B1LO 49152
#define S_Z2   0          /* fp32 z2, 128 x stride129 = 66048 B, reuses A1/B1 */
#define S_B2HI 66560
#define S_B2LO 99328
#define S_AVEC 132096     /* a_h vectors: 2 x 128 fp32 */
#define S_SS   133120     /* scores 128 x 2 fp32 */
#define S_SP   134144     /* score partials 128 x 2 x 2 fp32 */
#define S_CTRL 136192     /* tmem ptr @0, mbar @8, c[2] @16 */
#define S_B1B  136256     /* b1 128 fp32 */
#define S_B2B  136768     /* b2 128 fp32 */
#define S_TOTAL 137280    /* >= fallback's 137216 too */

// idesc: F32 accum, BF16 a/b, N=128, M=128, cta_group::1
#define IDESC ((1u<<4)|(1u<<7)|(1u<<10)|(16u<<17)|(8u<<24))

// Fallback smem geometry (floats)
#define US 68
#define ZS 132

// ---------------- global scratch (no allocations allowed) ----------------
__device__ float g_a[2 * 128];
__device__ float g_c[2];
__device__ float g_mp[TILES * BATCH * 256];
__device__ float g_Sp[TILES * BATCH * 2];
// Precomputed swizzled SMEM byte-images of W1^T / W2^T as split bf16 (TC path).
__device__ __align__(16) __nv_bfloat16 g_B1hi[128 * 64];
__device__ __align__(16) __nv_bfloat16 g_B1lo[128 * 64];
__device__ __align__(16) __nv_bfloat16 g_B2hi[128 * 128];
__device__ __align__(16) __nv_bfloat16 g_B2lo[128 * 128];

// ---------------- common helpers ----------------
__device__ __forceinline__ float gelu_f(float x) {
    float x2 = x * x;
    float inner = fmaf(0.044715f * x2, x, x);
    float arg = 0.7978845608028654f * inner;
    float t;
    asm("tanh.approx.f32 %0, %1;" : "=f"(t) : "f"(arg));
    return 0.5f * x * (1.0f + t);
}
__device__ __forceinline__ uint32_t swz(uint32_t byte_off) {
    return byte_off ^ ((byte_off >> 3) & 0x70);
}
__device__ __forceinline__ uint32_t pk_bf(float a, float b) {
    return (uint32_t)__bfloat16_as_ushort(__float2bfloat16_rn(a)) |
           ((uint32_t)__bfloat16_as_ushort(__float2bfloat16_rn(b)) << 16);
}
// fp32x2 helpers (fallback path)
__device__ __forceinline__ ULL pk2(float lo, float hi) {
    ULL r;
    asm("mov.b64 %0, {%1,%2};" : "=l"(r) : "f"(lo), "f"(hi));
    return r;
}
__device__ __forceinline__ void upk2(ULL v, float& lo, float& hi) {
    asm("mov.b64 {%0,%1}, %2;" : "=f"(lo), "=f"(hi) : "l"(v));
}
__device__ __forceinline__ void ffma2(ULL& d, ULL a, ULL b) {
    asm("fma.rn.f32x2 %0, %1, %2, %0;" : "+l"(d) : "l"(a), "l"(b));
}

#if TC_OK
// ---------------- tcgen05 PTX helpers (only compiled on 'a'/'f' targets) ----
__device__ __forceinline__ uint32_t elect_one_pred() {
    uint32_t pred;
    asm volatile(
        "{\n\t.reg .pred p;\n\telect.sync _|p, 0xFFFFFFFF;\n\t"
        "selp.b32 %0, 1, 0, p;\n\t}" : "=r"(pred));
    return pred;
}
__device__ __forceinline__ uint32_t smem_to_u32(const void* p) {
    uint32_t a;
    asm("{ .reg .u64 t; cvta.to.shared.u64 t, %1; cvt.u32.u64 %0, t; }" : "=r"(a) : "l"(p));
    return a;
}
static constexpr uint64_t SMEM_DESC_BASE_SW128 =
    (uint64_t(2) << 61) | (uint64_t(1) << 46) | (uint64_t(64) << 32) | (uint64_t(1) << 16);
#define MAKE_SMEM_DESC(base_addr) \
    (SMEM_DESC_BASE_SW128 | ((uint64_t)((base_addr) >> 4) & 0x3FFF))

#define TCGEN05_ALLOC(smem_addr, nCols) \
    asm volatile("tcgen05.alloc.cta_group::1.sync.aligned.shared::cta.b32 [%0], %1;" \
        :: "r"((uint32_t)(smem_addr)), "r"((uint32_t)(nCols)) : "memory")
#define TCGEN05_DEALLOC(tmem_addr, nCols) \
    asm volatile("tcgen05.dealloc.cta_group::1.sync.aligned.b32 %0, %1;" \
        :: "r"(tmem_addr), "r"((uint32_t)(nCols)))
#define TCGEN05_COMMIT(mbar) \
    asm volatile("tcgen05.commit.cta_group::1.mbarrier::arrive::one.shared::cluster.b64 [%0];" \
        :: "r"((uint32_t)(mbar)) : "memory")
#define TCGEN05_WAIT_LD()  asm volatile("tcgen05.wait::ld.sync.aligned;" ::: "memory")
#define TCGEN05_WAIT_ST()  asm volatile("tcgen05.wait::st.sync.aligned;" ::: "memory")
#define TCGEN05_FENCE_BEFORE() asm volatile("tcgen05.fence::before_thread_sync;" ::: "memory")
#define TCGEN05_FENCE_AFTER()  asm volatile("tcgen05.fence::after_thread_sync;" ::: "memory")
#define MBARRIER_INIT(mbar, count) \
    asm volatile("mbarrier.init.shared.b64 [%0], %1;" \
        :: "r"((uint32_t)(mbar)), "r"((uint32_t)(count)) : "memory")
#define MBARRIER_INVAL(mbar) \
    asm volatile("mbarrier.inval.shared.b64 [%0];" :: "r"((uint32_t)(mbar)) : "memory")

#define MBARRIER_WAIT_PARITY(mbar_smem_addr, phase_parity) do { \
    uint32_t _mbar = (uint32_t)(mbar_smem_addr); \
    uint32_t _parity = (uint32_t)(phase_parity); \
    uint32_t _done; \
    asm volatile( \
        "{\n\t.reg .pred p;\n\t" \
        "mbarrier.try_wait.parity.acquire.cta.shared::cta.b64 p, [%1], %2;\n\t" \
        "selp.b32 %0, 1, 0, p;\n\t}" \
        : "=r"(_done) : "r"(_mbar), "r"(_parity) : "memory"); \
    if (!_done) { \
        asm volatile( \
            "{\n\t.reg .pred P1;\n\t" \
            "WAIT_LOOP_%=:\n\t" \
            "mbarrier.try_wait.parity.acquire.cta.shared::cta.b64 P1, [%0], %1, 0x989680;\n\t" \
            "@P1 bra.uni WAIT_DONE_%=;\n\t" \
            "bra.uni WAIT_LOOP_%=;\n\t" \
            "WAIT_DONE_%=:\n\t}" \
            :: "r"(_mbar), "r"(_parity) : "memory"); \
    } \
} while (0)

#define TCGEN05_LD_32X32B_X32(r, tmem_addr) \
    asm volatile( \
        "tcgen05.ld.sync.aligned.32x32b.x32.b32 " \
        "{%0, %1, %2, %3, %4, %5, %6, %7, " \
        " %8, %9, %10, %11, %12, %13, %14, %15, " \
        " %16, %17, %18, %19, %20, %21, %22, %23, " \
        " %24, %25, %26, %27, %28, %29, %30, %31}, [%32];" \
        : "=r"((r)[0]),  "=r"((r)[1]),  "=r"((r)[2]),  "=r"((r)[3]), \
          "=r"((r)[4]),  "=r"((r)[5]),  "=r"((r)[6]),  "=r"((r)[7]), \
          "=r"((r)[8]),  "=r"((r)[9]),  "=r"((r)[10]), "=r"((r)[11]), \
          "=r"((r)[12]), "=r"((r)[13]), "=r"((r)[14]), "=r"((r)[15]), \
          "=r"((r)[16]), "=r"((r)[17]), "=r"((r)[18]), "=r"((r)[19]), \
          "=r"((r)[20]), "=r"((r)[21]), "=r"((r)[22]), "=r"((r)[23]), \
          "=r"((r)[24]), "=r"((r)[25]), "=r"((r)[26]), "=r"((r)[27]), \
          "=r"((r)[28]), "=r"((r)[29]), "=r"((r)[30]), "=r"((r)[31]) \
        : "r"(tmem_addr))

#define TCGEN05_ST_32X32B_X16(tmem_addr, r) \
    asm volatile( \
        "tcgen05.st.sync.aligned.32x32b.x16.b32 [%0], " \
        "{%1, %2, %3, %4, %5, %6, %7, %8, " \
        " %9, %10, %11, %12, %13, %14, %15, %16};" \
        :: "r"(tmem_addr), \
           "r"((r)[0]),  "r"((r)[1]),  "r"((r)[2]),  "r"((r)[3]), \
           "r"((r)[4]),  "r"((r)[5]),  "r"((r)[6]),  "r"((r)[7]), \
           "r"((r)[8]),  "r"((r)[9]),  "r"((r)[10]), "r"((r)[11]), \
           "r"((r)[12]), "r"((r)[13]), "r"((r)[14]), "r"((r)[15]) \
        : "memory")

__device__ __forceinline__ void mma_f16_ss(uint32_t d, uint64_t ad, uint64_t bd,
                                           uint32_t idesc, uint32_t en) {
    asm volatile(
        "{\n\t.reg .pred p;\n\tsetp.ne.u32 p, %4, 0;\n\t"
        "tcgen05.mma.cta_group::1.kind::f16 [%0], %1, %2, %3, {%5, %5, %5, %5}, p;\n\t}"
        :: "r"(d), "l"(ad), "l"(bd), "r"(idesc), "r"(en), "r"(0u) : "memory");
}
__device__ __forceinline__ void mma_f16_ts(uint32_t d, uint32_t at, uint64_t bd,
                                           uint32_t idesc, uint32_t en) {
    asm volatile(
        "{\n\t.reg .pred p;\n\tsetp.ne.u32 p, %4, 0;\n\t"
        "tcgen05.mma.cta_group::1.kind::f16 [%0], [%1], %2, %3, {%5, %5, %5, %5}, p;\n\t}"
        :: "r"(d), "r"(at), "l"(bd), "r"(idesc), "r"(en), "r"(0u) : "memory");
}
#endif  // TC_OK

// ---------------- prep: a/c vectors + W^T split-bf16 swizzled images ----------------
__global__ void prep_kernel(const float* __restrict__ embed,
                            const float* __restrict__ Wq, const float* __restrict__ bq,
                            const float* __restrict__ Wk, const float* __restrict__ bk,
                            const float* __restrict__ W1, const float* __restrict__ W2) {
    int t = threadIdx.x;
    if (blockIdx.x == 0) {
        __shared__ float sq[128];
        if (t < 128) {
            float q = bq[t];
            #pragma unroll 8
            for (int c = 0; c < 128; c++) q = fmaf(embed[c], Wq[c * 128 + t], q);
            sq[t] = q;
        }
        __syncthreads();
        if (t < 128) {
            float a0 = 0.f, a1 = 0.f;
            #pragma unroll 8
            for (int d = 0; d < 64; d++) {
                a0 = fmaf(Wk[t * 128 + d], sq[d], a0);
                a1 = fmaf(Wk[t * 128 + 64 + d], sq[64 + d], a1);
            }
            g_a[t] = a0;
            g_a[128 + t] = a1;
        }
        if (t < 2) {
            float c0 = 0.f;
            #pragma unroll 8
            for (int d = 0; d < 64; d++) c0 = fmaf(bk[t * 64 + d], sq[t * 64 + d], c0);
            g_c[t] = c0;
        }
    } else if (blockIdx.x == 1) {
        // B1[n][k] = W1[k][n], K-major bf16 rows of 128B, SW128 swizzled image
        for (int idx = t; idx < 128 * 64; idx += 256) {
            int k = idx >> 7, n = idx & 127;
            float wv = W1[idx];
            __nv_bfloat16 h = __float2bfloat16_rn(wv);
            __nv_bfloat16 l = __float2bfloat16_rn(wv - __bfloat162float(h));
            uint32_t sw = swz((uint32_t)(n * 128 + k * 2));
            g_B1hi[sw >> 1] = h;
            g_B1lo[sw >> 1] = l;
        }
    } else {
        // B2[n][k] = W2[k][n], blocked SW128 atoms: atom_col(k/64) stride 16KB
        for (int idx = t; idx < 128 * 128; idx += 256) {
            int k = idx >> 7, n = idx & 127;
            float wv = W2[idx];
            __nv_bfloat16 h = __float2bfloat16_rn(wv);
            __nv_bfloat16 l = __float2bfloat16_rn(wv - __bfloat162float(h));
            uint32_t byte = ((uint32_t)(k >> 6) << 14) + ((uint32_t)(n >> 3) << 10)
                          + ((uint32_t)(n & 7) << 7) + ((uint32_t)(k & 63) << 1);
            uint32_t sw = swz(byte);
            g_B2hi[sw >> 1] = h;
            g_B2lo[sw >> 1] = l;
        }
    }
}

// ---------------- main kernel: one symbol, arch-selected body ----------------
__global__ void __launch_bounds__(256, 1)
main_kernel(const float* __restrict__ u,
            const float* __restrict__ W1, const float* __restrict__ b1,
            const float* __restrict__ W2, const float* __restrict__ b2) {
#if TC_OK
    // ================= tcgen05 split-bf16 path =================
    extern __shared__ char sb[];
    const int tid = threadIdx.x;
    const int w = tid >> 5;
    const int lane = tid & 31;
    const int tile = blockIdx.x;
    const int b = blockIdx.y;
    uint32_t sb32 = smem_to_u32(sb);

    if (w == 0) TCGEN05_ALLOC(sb32 + S_CTRL, TMEM_COLS);
    if (tid == 0) MBARRIER_INIT(sb32 + S_CTRL + 8, 1);

    // ---- phase 0: u tile -> split-bf16 A1 (SW128 K-major), copy B1 image ----
    {
        int row = tid >> 1, kh = (tid & 1) << 5;
        const float4* up = (const float4*)(u + ((size_t)b * SEQN + (size_t)tile * 128 + row) * 64 + kh);
        #pragma unroll
        for (int i = 0; i < 8; i++) {
            float4 v = up[i];
            __nv_bfloat16 h0 = __float2bfloat16_rn(v.x), h1 = __float2bfloat16_rn(v.y);
            __nv_bfloat16 h2 = __float2bfloat16_rn(v.z), h3 = __float2bfloat16_rn(v.w);
            uint32_t hiA = (uint32_t)__bfloat16_as_ushort(h0) | ((uint32_t)__bfloat16_as_ushort(h1) << 16);
            uint32_t hiB = (uint32_t)__bfloat16_as_ushort(h2) | ((uint32_t)__bfloat16_as_ushort(h3) << 16);
            uint32_t loA = pk_bf(v.x - __bfloat162float(h0), v.y - __bfloat162float(h1));
            uint32_t loB = pk_bf(v.z - __bfloat162float(h2), v.w - __bfloat162float(h3));
            uint32_t sw = swz((uint32_t)(row * 128 + (kh + 4 * i) * 2));
            *(ULL*)(sb + S_A1HI + sw) = (ULL)hiA | ((ULL)hiB << 32);
            *(ULL*)(sb + S_A1LO + sw) = (ULL)loA | ((ULL)loB << 32);
        }
    }
    {
        const float4* gh = (const float4*)g_B1hi;
        const float4* gl = (const float4*)g_B1lo;
        float4* sh = (float4*)(sb + S_B1HI);
        float4* sl = (float4*)(sb + S_B1LO);
        #pragma unroll
        for (int i = 0; i < 4; i++) {
            sh[tid + i * 256] = gh[tid + i * 256];
            sl[tid + i * 256] = gl[tid + i * 256];
        }
    }
    ((float*)(sb + S_AVEC))[tid] = g_a[tid];
    if (tid < 128) {
        ((float*)(sb + S_B1B))[tid] = b1[tid];
        ((float*)(sb + S_B2B))[tid] = b2[tid];
    }
    if (tid < 2) ((float*)(sb + S_CTRL + 16))[tid] = g_c[tid];
    asm volatile("fence.proxy.async.shared::cta;" ::: "memory");
    __syncthreads();

    uint32_t tbase;
    asm volatile("ld.shared.b32 %0, [%1];" : "=r"(tbase) : "r"(sb32 + S_CTRL));

    // ---- GEMM1: D1 = A1 @ B1^T  (3 split terms x 4 K-chunks, SS mode) ----
    if (w == 0) {
        uint64_t aH = MAKE_SMEM_DESC(sb32 + S_A1HI), aL = MAKE_SMEM_DESC(sb32 + S_A1LO);
        uint64_t bH = MAKE_SMEM_DESC(sb32 + S_B1HI), bL = MAKE_SMEM_DESC(sb32 + S_B1LO);
        if (elect_one_pred()) {
            #pragma unroll
            for (int k = 0; k < 4; k++) mma_f16_ss(tbase + T_D1, aH + 2 * k, bH + 2 * k, IDESC, k > 0);
            #pragma unroll
            for (int k = 0; k < 4; k++) mma_f16_ss(tbase + T_D1, aH + 2 * k, bL + 2 * k, IDESC, 1);
            #pragma unroll
            for (int k = 0; k < 4; k++) mma_f16_ss(tbase + T_D1, aL + 2 * k, bH + 2 * k, IDESC, 1);
            TCGEN05_COMMIT(sb32 + S_CTRL + 8);
        }
    }
    // ---- copy B2 image while GEMM1 runs ----
    {
        const float4* gh = (const float4*)g_B2hi;
        const float4* gl = (const float4*)g_B2lo;
        float4* sh = (float4*)(sb + S_B2HI);
        float4* sl = (float4*)(sb + S_B2LO);
        #pragma unroll
        for (int i = 0; i < 8; i++) {
            sh[tid + i * 256] = gh[tid + i * 256];
            sl[tid + i * 256] = gl[tid + i * 256];
        }
    }
    asm volatile("fence.proxy.async.shared::cta;" ::: "memory");

    MBARRIER_WAIT_PARITY(sb32 + S_CTRL + 8, 0);
    TCGEN05_FENCE_AFTER();

    // ---- epilogue 1: z1 = gelu(D1+b1) -> split bf16 -> TMEM A2 (TS operand) ----
    const int part = w & 3;
    const int cbase = (w >> 2) * 64;
    const int r = part * 32 + lane;
    const uint32_t sttm = ((uint32_t)part) << 21;
    {
        const float* b1s = (const float*)(sb + S_B1B);
        #pragma unroll
        for (int ch = 0; ch < 2; ch++) {
            int c0 = cbase + 32 * ch;
            uint32_t d[32];
            TCGEN05_LD_32X32B_X32(d, tbase + T_D1 + c0);
            TCGEN05_WAIT_LD();
            uint32_t hi[16], lo[16];
            #pragma unroll
            for (int j = 0; j < 16; j++) {
                float z0 = gelu_f(__uint_as_float(d[2 * j]) + b1s[c0 + 2 * j]);
                float z1 = gelu_f(__uint_as_float(d[2 * j + 1]) + b1s[c0 + 2 * j + 1]);
                __nv_bfloat16 h0 = __float2bfloat16_rn(z0), h1 = __float2bfloat16_rn(z1);
                hi[j] = (uint32_t)__bfloat16_as_ushort(h0) | ((uint32_t)__bfloat16_as_ushort(h1) << 16);
                lo[j] = pk_bf(z0 - __bfloat162float(h0), z1 - __bfloat162float(h1));
            }
            TCGEN05_ST_32X32B_X16(tbase + T_A2HI + (c0 >> 1) + sttm, hi);
            TCGEN05_ST_32X32B_X16(tbase + T_A2LO + (c0 >> 1) + sttm, lo);
        }
        TCGEN05_WAIT_ST();
    }
    TCGEN05_FENCE_BEFORE();
    __syncthreads();

    // ---- GEMM2: D2 = A2 @ B2^T  (3 split terms x 8 K-chunks, TS mode) ----
    if (w == 0) {
        TCGEN05_FENCE_AFTER();
        uint64_t bH = MAKE_SMEM_DESC(sb32 + S_B2HI), bL = MAKE_SMEM_DESC(sb32 + S_B2LO);
        if (elect_one_pred()) {
            #pragma unroll
            for (int k = 0; k < 8; k++) {
                uint64_t o = (k < 4) ? (uint64_t)(2 * k) : (uint64_t)(1024 + 2 * (k - 4));
                mma_f16_ts(tbase + T_D2, tbase + T_A2HI + 8 * k, bH + o, IDESC, k > 0);
            }
            #pragma unroll
            for (int k = 0; k < 8; k++) {
                uint64_t o = (k < 4) ? (uint64_t)(2 * k) : (uint64_t)(1024 + 2 * (k - 4));
                mma_f16_ts(tbase + T_D2, tbase + T_A2HI + 8 * k, bL + o, IDESC, 1);
            }
            #pragma unroll
            for (int k = 0; k < 8; k++) {
                uint64_t o = (k < 4) ? (uint64_t)(2 * k) : (uint64_t)(1024 + 2 * (k - 4));
                mma_f16_ts(tbase + T_D2, tbase + T_A2LO + 8 * k, bH + o, IDESC, 1);
            }
            TCGEN05_COMMIT(sb32 + S_CTRL + 8);
        }
    }
    MBARRIER_WAIT_PARITY(sb32 + S_CTRL + 8, 1);
    TCGEN05_FENCE_AFTER();

    // ---- epilogue 2: z2 = gelu(D2+b2); score partials; z2 -> smem (stride 129) ----
    {
        float* z2s = (float*)(sb + S_Z2);
        const float* av = (const float*)(sb + S_AVEC);
        const float* b2s = (const float*)(sb + S_B2B);
        float sp0 = 0.f, sp1 = 0.f;
        #pragma unroll
        for (int ch = 0; ch < 2; ch++) {
            int c0 = cbase + 32 * ch;
            uint32_t d[32];
            TCGEN05_LD_32X32B_X32(d, tbase + T_D2 + c0);
            TCGEN05_WAIT_LD();
            #pragma unroll
            for (int j = 0; j < 32; j++) {
                float z = gelu_f(__uint_as_float(d[j]) + b2s[c0 + j]);
                z2s[r * 129 + c0 + j] = z;
                sp0 = fmaf(av[c0 + j], z, sp0);
                sp1 = fmaf(av[128 + c0 + j], z, sp1);
            }
        }
        float* sSp = (float*)(sb + S_SP);
        sSp[r * 4 + (w >> 2) * 2 + 0] = sp0;
        sSp[r * 4 + (w >> 2) * 2 + 1] = sp1;
    }
    __syncthreads();

    // combine score halves: s[r][h] = c_h + sp[r][0][h] + sp[r][1][h]
    {
        float* sS = (float*)(sb + S_SS);
        const float* sSp = (const float*)(sb + S_SP);
        const float* cs = (const float*)(sb + S_CTRL + 16);
        int r2 = tid >> 1, h = tid & 1;
        sS[r2 * 2 + h] = cs[h] + sSp[r2 * 4 + h] + sSp[r2 * 4 + 2 + h];
    }
    __syncthreads();

    // phase 4: m_h[col] = sum_r s[r][h] * z2[r][col]
    {
        const float* sS = (const float*)(sb + S_SS);
        const float* z2s = (const float*)(sb + S_Z2);
        int h = tid >> 7, col = tid & 127;
        float m = 0.f;
        #pragma unroll 4
        for (int rr = 0; rr < 128; rr++) m = fmaf(sS[rr * 2 + h], z2s[rr * 129 + col], m);
        g_mp[((size_t)(tile * BATCH + b)) * 256 + tid] = m;
        if (tid < 2) {
            float S = 0.f;
            #pragma unroll 4
            for (int rr = 0; rr < 128; rr++) S += sS[rr * 2 + tid];
            g_Sp[(tile * BATCH + b) * 2 + tid] = S;
        }
    }

    __syncthreads();
    if (tid == 0) MBARRIER_INVAL(sb32 + S_CTRL + 8);
    __syncthreads();
    if (w == 0) TCGEN05_DEALLOC(tbase, TMEM_COLS);

#else
    // ================= proven FFMA f32x2 fallback (191us path) =================
    extern __shared__ float smem[];
    float* sU = smem;
    float* sW1 = smem + 8704;
    float* sW2 = smem;          // reuses region A after GEMM1
    float* sZ = smem + 16896;
    float* sS = smem + 33792;
    float* sA = smem + 34048;

    const int tid = threadIdx.x;
    const int tx = tid & 15;
    const int ty = tid >> 4;
    const int tile = blockIdx.x;
    const int b = blockIdx.y;

    {
        const float4* uT = (const float4*)(u + ((size_t)b * SEQN + (size_t)tile * 128) * 64);
        float4* sUv = (float4*)sU;
        #pragma unroll
        for (int i = 0; i < 8; i++) {
            int idx = tid + i * 256;
            int row = idx >> 4, q = idx & 15;
            sUv[row * 17 + q] = uT[idx];
        }
        float4* sW1v = (float4*)sW1;
        const float4* W1v = (const float4*)W1;
        #pragma unroll
        for (int i = 0; i < 8; i++) sW1v[tid + i * 256] = W1v[tid + i * 256];
        sA[tid] = g_a[tid];
    }
    __syncthreads();

    ULL acc[8][4];
    #pragma unroll
    for (int i = 0; i < 8; i++)
        #pragma unroll
        for (int j = 0; j < 4; j++) acc[i][j] = 0ULL;

    #pragma unroll 2
    for (int k = 0; k < 64; k++) {
        ULL a2[8];
        #pragma unroll
        for (int i = 0; i < 8; i++) {
            float av = sU[(ty + 16 * i) * US + k];
            a2[i] = pk2(av, av);
        }
        const ulonglong2* wr = (const ulonglong2*)(sW1 + k * 128);
        ulonglong2 w0 = wr[tx];
        ulonglong2 w1 = wr[16 + tx];
        ULL bb0 = w0.x, bb1 = w0.y, bb2 = w1.x, bb3 = w1.y;
        #pragma unroll
        for (int i = 0; i < 8; i++) {
            ffma2(acc[i][0], a2[i], bb0);
            ffma2(acc[i][1], a2[i], bb1);
            ffma2(acc[i][2], a2[i], bb2);
            ffma2(acc[i][3], a2[i], bb3);
        }
    }
    {
        float4 bA = ((const float4*)b1)[tx];
        float4 bB = ((const float4*)b1)[16 + tx];
        #pragma unroll
        for (int i = 0; i < 8; i++) {
            int row = ty + 16 * i;
            float x0, x1, x2, x3, y0, y1, y2, y3;
            upk2(acc[i][0], x0, x1);
            upk2(acc[i][1], x2, x3);
            upk2(acc[i][2], y0, y1);
            upk2(acc[i][3], y2, y3);
            float4 o0 = make_float4(gelu_f(x0 + bA.x), gelu_f(x1 + bA.y),
                                    gelu_f(x2 + bA.z), gelu_f(x3 + bA.w));
            float4 o1 = make_float4(gelu_f(y0 + bB.x), gelu_f(y1 + bB.y),
                                    gelu_f(y2 + bB.z), gelu_f(y3 + bB.w));
            float4* zr = (float4*)(sZ + row * ZS);
            zr[tx] = o0;
            zr[16 + tx] = o1;
        }
    }
    __syncthreads();

    {
        float4* sW2v = (float4*)sW2;
        const float4* W2v = (const float4*)W2;
        #pragma unroll
        for (int i = 0; i < 16; i++) sW2v[tid + i * 256] = W2v[tid + i * 256];
    }
    __syncthreads();

    #pragma unroll
    for (int i = 0; i < 8; i++)
        #pragma unroll
        for (int j = 0; j < 4; j++) acc[i][j] = 0ULL;

    #pragma unroll 2
    for (int k = 0; k < 128; k++) {
        ULL a2[8];
        #pragma unroll
        for (int i = 0; i < 8; i++) {
            float av = sZ[(ty + 16 * i) * ZS + k];
            a2[i] = pk2(av, av);
        }
        const ulonglong2* wr = (const ulonglong2*)(sW2 + k * 128);
        ulonglong2 w0 = wr[tx];
        ulonglong2 w1 = wr[16 + tx];
        ULL bb0 = w0.x, bb1 = w0.y, bb2 = w1.x, bb3 = w1.y;
        #pragma unroll
        for (int i = 0; i < 8; i++) {
            ffma2(acc[i][0], a2[i], bb0);
            ffma2(acc[i][1], a2[i], bb1);
            ffma2(acc[i][2], a2[i], bb2);
            ffma2(acc[i][3], a2[i], bb3);
        }
    }
    __syncthreads();
    {
        float4 bA = ((const float4*)b2)[tx];
        float4 bB = ((const float4*)b2)[16 + tx];
        #pragma unroll
        for (int i = 0; i < 8; i++) {
            int row = ty + 16 * i;
            float x0, x1, x2, x3, y0, y1, y2, y3;
            upk2(acc[i][0], x0, x1);
            upk2(acc[i][1], x2, x3);
            upk2(acc[i][2], y0, y1);
            upk2(acc[i][3], y2, y3);
            float4 o0 = make_float4(gelu_f(x0 + bA.x), gelu_f(x1 + bA.y),
                                    gelu_f(x2 + bA.z), gelu_f(x3 + bA.w));
            float4 o1 = make_float4(gelu_f(y0 + bB.x), gelu_f(y1 + bB.y),
                                    gelu_f(y2 + bB.z), gelu_f(y3 + bB.w));
            float4* zr = (float4*)(sZ + row * ZS);
            zr[tx] = o0;
            zr[16 + tx] = o1;
        }
    }
    __syncthreads();

    {
        int rr = tid >> 1, h = tid & 1;
        const float4* ar = (const float4*)(sA + h * 128);
        const float4* zr = (const float4*)(sZ + rr * ZS);
        float s = g_c[h];
        #pragma unroll 8
        for (int c = 0; c < 32; c++) {
            float4 zz = zr[c];
            float4 aa = ar[c];
            s = fmaf(zz.x, aa.x, s);
            s = fmaf(zz.y, aa.y, s);
            s = fmaf(zz.z, aa.z, s);
            s = fmaf(zz.w, aa.w, s);
        }
        sS[rr * 2 + h] = s;
    }
    __syncthreads();

    {
        int h = tid >> 7, col = tid & 127;
        float accm = 0.f;
        #pragma unroll 4
        for (int rr = 0; rr < 128; rr++) accm = fmaf(sS[rr * 2 + h], sZ[rr * ZS + col], accm);
        g_mp[((size_t)(tile * BATCH + b)) * 256 + tid] = accm;
        if (tid < 2) {
            float S = 0.f;
            #pragma unroll 4
            for (int rr = 0; rr < 128; rr++) S += sS[rr * 2 + tid];
            g_Sp[(tile * BATCH + b) * 2 + tid] = S;
        }
    }
#endif
}

// ---------------- finish: reduce partials, V-proj, O-proj ----------------
__global__ void finish_kernel(const float* __restrict__ Wv, const float* __restrict__ bv,
                              const float* __restrict__ Wo, const float* __restrict__ bo,
                              float* __restrict__ out) {
    __shared__ float sm[256];
    __shared__ float sSs[2];
    __shared__ float sop[128];
    int b = blockIdx.x;
    int t = threadIdx.x;  // 128 threads
    float m0 = 0.f, m1 = 0.f;
    for (int tile = 0; tile < TILES; tile++) {
        const float* p = g_mp + ((size_t)(tile * BATCH + b)) * 256;
        m0 += p[t];
        m1 += p[128 + t];
    }
    sm[t] = m0;
    sm[128 + t] = m1;
    if (t < 2) {
        float S = 0.f;
        for (int tile = 0; tile < TILES; tile++) S += g_Sp[(tile * BATCH + b) * 2 + t];
        sSs[t] = S;
    }
    __syncthreads();
    int h = t >> 6;
    float acc = 0.f;
    #pragma unroll 4
    for (int d = 0; d < 128; d++) acc = fmaf(sm[h * 128 + d], Wv[d * 128 + t], acc);
    acc = (acc + sSs[h] * bv[t]) * (1.0f / (float)SEQN);
    sop[t] = acc;
    __syncthreads();
    float o = bo[t];
    #pragma unroll 4
    for (int j = 0; j < 128; j++) o = fmaf(sop[j], Wo[j * 128 + t], o);
    out[b * 128 + t] = o;
}

// ---------------- launch ----------------
extern "C" void kernel_launch(void* const* d_in, const int* in_sizes, int n_in,
                              void* d_out, int out_size) {
    const float* u     = (const float*)d_in[0];
    // d_in[1] = x, unused by the reference output
    const float* W1    = (const float*)d_in[2];
    const float* b1    = (const float*)d_in[3];
    const float* W2    = (const float*)d_in[4];
    const float* b2    = (const float*)d_in[5];
    const float* embed = (const float*)d_in[6];
    const float* Wq    = (const float*)d_in[7];
    const float* bq    = (const float*)d_in[8];
    const float* Wk    = (const float*)d_in[9];
    const float* bk    = (const float*)d_in[10];
    const float* Wv    = (const float*)d_in[11];
    const float* bv    = (const float*)d_in[12];
    const float* Wo    = (const float*)d_in[13];
    const float* bo    = (const float*)d_in[14];
    float* out = (float*)d_out;

    cudaFuncSetAttribute(main_kernel, cudaFuncAttributeMaxDynamicSharedMemorySize, S_TOTAL);

    prep_kernel<<<3, 256>>>(embed, Wq, bq, Wk, bk, W1, W2);
    main_kernel<<<dim3(TILES, BATCH), 256, S_TOTAL>>>(u, W1, b1, W2, b2);
    finish_kernel<<<BATCH, 128>>>(Wv, bv, Wo, bo, out);
}

// round 7
// speedup vs baseline: 1.5835x; 1.0069x over previous
#include <cuda_runtime.h>
#include <cuda_bf16.h>
#include <cstdint>
#include <cstddef>

// Problem constants: B=32, N=4096, D_U=64, D=128, H=2, DH=64
#define BATCH 32
#define SEQN 4096
#define TILES 32

typedef unsigned long long ULL;

// ---- arch-feature gate: tcgen05 only exists on 'a'/'f' suffixed targets ----
#if defined(__CUDA_ARCH__) && (__CUDA_ARCH__ >= 1000) && \
    (defined(__CUDA_ARCH_FEAT_SM103_ALL) || defined(__CUDA_ARCH_FEAT_SM100_ALL) || \
     defined(__CUDA_ARCH_SPECIFIC__) || defined(__CUDA_ARCH_FAMILY_SPECIFIC__))
#define TC_OK 1
#else
#define TC_OK 0
#endif

// ---------------- TMEM column layout (TC path): 256 cols total ----------------
#define T_A2HI 0
#define T_A2LO 64
#define T_D    128      /* shared by D1 (GEMM1) and D2 (GEMM2) */
#define TMEM_COLS 256

// ---------------- SMEM layout (bytes), slim: 2 CTAs/SM ----------------
// Phase A (until GEMM1 done):  A1hi@0, A1lo@16K, B1hi@32K, B1lo@48K
// Phase B (GEMM2):             B2hi@0 (32K), B2lo@32K (32K)
// Phase C (epi2 on):           z2 fp32 @0, 128 x stride129 = 66048 B
#define S_A1HI 0
#define S_A1LO 16384
#define S_B1HI 32768
#define S_B1LO 49152
#define S_B2HI 0
#define S_B2LO 32768
#define S_Z2   0
#define S_AVEC 66560      /* a_h vectors: 2 x 128 fp32 */
#define S_SS   67584      /* scores 128 x 2 fp32 */
#define S_SP   68608      /* score partials 128 x 2 x 2 fp32 */
#define S_CTRL 70656      /* tmem ptr @0, mbar @8, c[2] @16 */
#define S_B1B  70720      /* b1 128 fp32 */
#define S_B2B  71232      /* b2 128 fp32 */
#define S_TOTAL 71744

// idesc: F32 accum, BF16 a/b, N=128, M=128, cta_group::1
#define IDESC ((1u<<4)|(1u<<7)|(1u<<10)|(16u<<17)|(8u<<24))

// ---------------- global scratch (no allocations allowed) ----------------
__device__ float g_a[2 * 128];
__device__ float g_c[2];
__device__ float g_mp[TILES * BATCH * 256];
__device__ float g_Sp[TILES * BATCH * 2];
// Precomputed swizzled SMEM byte-images of W1^T / W2^T as split bf16 (TC path).
__device__ __align__(16) __nv_bfloat16 g_B1hi[128 * 64];
__device__ __align__(16) __nv_bfloat16 g_B1lo[128 * 64];
__device__ __align__(16) __nv_bfloat16 g_B2hi[128 * 128];
__device__ __align__(16) __nv_bfloat16 g_B2lo[128 * 128];

// ---------------- common helpers ----------------
__device__ __forceinline__ float gelu_f(float x) {
    float x2 = x * x;
    float inner = fmaf(0.044715f * x2, x, x);
    float arg = 0.7978845608028654f * inner;
    float t;
    asm("tanh.approx.f32 %0, %1;" : "=f"(t) : "f"(arg));
    return 0.5f * x * (1.0f + t);
}
__device__ __forceinline__ uint32_t swz(uint32_t byte_off) {
    return byte_off ^ ((byte_off >> 3) & 0x70);
}
__device__ __forceinline__ uint32_t pk_bf(float a, float b) {
    return (uint32_t)__bfloat16_as_ushort(__float2bfloat16_rn(a)) |
           ((uint32_t)__bfloat16_as_ushort(__float2bfloat16_rn(b)) << 16);
}

#if TC_OK
// ---------------- tcgen05 PTX helpers (only compiled on 'a'/'f' targets) ----
__device__ __forceinline__ uint32_t elect_one_pred() {
    uint32_t pred;
    asm volatile(
        "{\n\t.reg .pred p;\n\telect.sync _|p, 0xFFFFFFFF;\n\t"
        "selp.b32 %0, 1, 0, p;\n\t}" : "=r"(pred));
    return pred;
}
__device__ __forceinline__ uint32_t smem_to_u32(const void* p) {
    uint32_t a;
    asm("{ .reg .u64 t; cvta.to.shared.u64 t, %1; cvt.u32.u64 %0, t; }" : "=r"(a) : "l"(p));
    return a;
}
static constexpr uint64_t SMEM_DESC_BASE_SW128 =
    (uint64_t(2) << 61) | (uint64_t(1) << 46) | (uint64_t(64) << 32) | (uint64_t(1) << 16);
#define MAKE_SMEM_DESC(base_addr) \
    (SMEM_DESC_BASE_SW128 | ((uint64_t)((base_addr) >> 4) & 0x3FFF))

#define TCGEN05_ALLOC(smem_addr, nCols) \
    asm volatile("tcgen05.alloc.cta_group::1.sync.aligned.shared::cta.b32 [%0], %1;" \
        :: "r"((uint32_t)(smem_addr)), "r"((uint32_t)(nCols)) : "memory")
#define TCGEN05_DEALLOC(tmem_addr, nCols) \
    asm volatile("tcgen05.dealloc.cta_group::1.sync.aligned.b32 %0, %1;" \
        :: "r"(tmem_addr), "r"((uint32_t)(nCols)))
#define TCGEN05_COMMIT(mbar) \
    asm volatile("tcgen05.commit.cta_group::1.mbarrier::arrive::one.shared::cluster.b64 [%0];" \
        :: "r"((uint32_t)(mbar)) : "memory")
#define TCGEN05_WAIT_LD()  asm volatile("tcgen05.wait::ld.sync.aligned;" ::: "memory")
#define TCGEN05_WAIT_ST()  asm volatile("tcgen05.wait::st.sync.aligned;" ::: "memory")
#define TCGEN05_FENCE_BEFORE() asm volatile("tcgen05.fence::before_thread_sync;" ::: "memory")
#define TCGEN05_FENCE_AFTER()  asm volatile("tcgen05.fence::after_thread_sync;" ::: "memory")
#define MBARRIER_INIT(mbar, count) \
    asm volatile("mbarrier.init.shared.b64 [%0], %1;" \
        :: "r"((uint32_t)(mbar)), "r"((uint32_t)(count)) : "memory")
#define MBARRIER_INVAL(mbar) \
    asm volatile("mbarrier.inval.shared.b64 [%0];" :: "r"((uint32_t)(mbar)) : "memory")

#define MBARRIER_WAIT_PARITY(mbar_smem_addr, phase_parity) do { \
    uint32_t _mbar = (uint32_t)(mbar_smem_addr); \
    uint32_t _parity = (uint32_t)(phase_parity); \
    uint32_t _done; \
    asm volatile( \
        "{\n\t.reg .pred p;\n\t" \
        "mbarrier.try_wait.parity.acquire.cta.shared::cta.b64 p, [%1], %2;\n\t" \
        "selp.b32 %0, 1, 0, p;\n\t}" \
        : "=r"(_done) : "r"(_mbar), "r"(_parity) : "memory"); \
    if (!_done) { \
        asm volatile( \
            "{\n\t.reg .pred P1;\n\t" \
            "WAIT_LOOP_%=:\n\t" \
            "mbarrier.try_wait.parity.acquire.cta.shared::cta.b64 P1, [%0], %1, 0x989680;\n\t" \
            "@P1 bra.uni WAIT_DONE_%=;\n\t" \
            "bra.uni WAIT_LOOP_%=;\n\t" \
            "WAIT_DONE_%=:\n\t}" \
            :: "r"(_mbar), "r"(_parity) : "memory"); \
    } \
} while (0)

#define TCGEN05_LD_32X32B_X32(r, tmem_addr) \
    asm volatile( \
        "tcgen05.ld.sync.aligned.32x32b.x32.b32 " \
        "{%0, %1, %2, %3, %4, %5, %6, %7, " \
        " %8, %9, %10, %11, %12, %13, %14, %15, " \
        " %16, %17, %18, %19, %20, %21, %22, %23, " \
        " %24, %25, %26, %27, %28, %29, %30, %31}, [%32];" \
        : "=r"((r)[0]),  "=r"((r)[1]),  "=r"((r)[2]),  "=r"((r)[3]), \
          "=r"((r)[4]),  "=r"((r)[5]),  "=r"((r)[6]),  "=r"((r)[7]), \
          "=r"((r)[8]),  "=r"((r)[9]),  "=r"((r)[10]), "=r"((r)[11]), \
          "=r"((r)[12]), "=r"((r)[13]), "=r"((r)[14]), "=r"((r)[15]), \
          "=r"((r)[16]), "=r"((r)[17]), "=r"((r)[18]), "=r"((r)[19]), \
          "=r"((r)[20]), "=r"((r)[21]), "=r"((r)[22]), "=r"((r)[23]), \
          "=r"((r)[24]), "=r"((r)[25]), "=r"((r)[26]), "=r"((r)[27]), \
          "=r"((r)[28]), "=r"((r)[29]), "=r"((r)[30]), "=r"((r)[31]) \
        : "r"(tmem_addr))

#define TCGEN05_ST_32X32B_X16(tmem_addr, r) \
    asm volatile( \
        "tcgen05.st.sync.aligned.32x32b.x16.b32 [%0], " \
        "{%1, %2, %3, %4, %5, %6, %7, %8, " \
        " %9, %10, %11, %12, %13, %14, %15, %16};" \
        :: "r"(tmem_addr), \
           "r"((r)[0]),  "r"((r)[1]),  "r"((r)[2]),  "r"((r)[3]), \
           "r"((r)[4]),  "r"((r)[5]),  "r"((r)[6]),  "r"((r)[7]), \
           "r"((r)[8]),  "r"((r)[9]),  "r"((r)[10]), "r"((r)[11]), \
           "r"((r)[12]), "r"((r)[13]), "r"((r)[14]), "r"((r)[15]) \
        : "memory")

__device__ __forceinline__ void mma_f16_ss(uint32_t d, uint64_t ad, uint64_t bd,
                                           uint32_t idesc, uint32_t en) {
    asm volatile(
        "{\n\t.reg .pred p;\n\tsetp.ne.u32 p, %4, 0;\n\t"
        "tcgen05.mma.cta_group::1.kind::f16 [%0], %1, %2, %3, {%5, %5, %5, %5}, p;\n\t}"
        :: "r"(d), "l"(ad), "l"(bd), "r"(idesc), "r"(en), "r"(0u) : "memory");
}
__device__ __forceinline__ void mma_f16_ts(uint32_t d, uint32_t at, uint64_t bd,
                                           uint32_t idesc, uint32_t en) {
    asm volatile(
        "{\n\t.reg .pred p;\n\tsetp.ne.u32 p, %4, 0;\n\t"
        "tcgen05.mma.cta_group::1.kind::f16 [%0], [%1], %2, %3, {%5, %5, %5, %5}, p;\n\t}"
        :: "r"(d), "r"(at), "l"(bd), "r"(idesc), "r"(en), "r"(0u) : "memory");
}
#endif  // TC_OK

// ---------------- prep: a/c vectors + W^T split-bf16 swizzled images ----------------
// Images are staged in SMEM (cheap scattered st.16) and written out with
// coalesced float4 stores. Grid = 17 blocks x 256 threads.
__global__ void prep_kernel(const float* __restrict__ embed,
                            const float* __restrict__ Wq, const float* __restrict__ bq,
                            const float* __restrict__ Wk, const float* __restrict__ bk,
                            const float* __restrict__ W1, const float* __restrict__ W2) {
    int t = threadIdx.x;
    int bx = blockIdx.x;
    if (bx == 0) {
        __shared__ float sq[128];
        if (t < 128) {
            float q = bq[t];
            #pragma unroll 8
            for (int c = 0; c < 128; c++) q = fmaf(embed[c], Wq[c * 128 + t], q);
            sq[t] = q;
        }
        __syncthreads();
        if (t < 128) {
            float a0 = 0.f, a1 = 0.f;
            #pragma unroll 8
            for (int d = 0; d < 64; d++) {
                a0 = fmaf(Wk[t * 128 + d], sq[d], a0);
                a1 = fmaf(Wk[t * 128 + 64 + d], sq[64 + d], a1);
            }
            g_a[t] = a0;
            g_a[128 + t] = a1;
        }
        if (t < 2) {
            float c0 = 0.f;
            #pragma unroll 8
            for (int d = 0; d < 64; d++) c0 = fmaf(bk[t * 64 + d], sq[t * 64 + d], c0);
            g_c[t] = c0;
        }
    } else if (bx <= 8) {
        // W1 image chunk: n in [n0, n0+16). B1[n][k]=W1[k][n], K-major SW128.
        __shared__ __align__(16) char stH[2048];
        __shared__ __align__(16) char stL[2048];
        int n0 = (bx - 1) * 16;
        #pragma unroll
        for (int i = 0; i < 4; i++) {
            int idx = t + 256 * i;          // 0..1023 : k = idx>>4, nl = idx&15
            int k = idx >> 4, nl = idx & 15;
            float wv = W1[k * 128 + n0 + nl];
            __nv_bfloat16 h = __float2bfloat16_rn(wv);
            __nv_bfloat16 l = __float2bfloat16_rn(wv - __bfloat162float(h));
            uint32_t loc = swz((uint32_t)(nl * 128 + k * 2));
            *(__nv_bfloat16*)(stH + loc) = h;
            *(__nv_bfloat16*)(stL + loc) = l;
        }
        __syncthreads();
        if (t < 128) {
            ((float4*)((char*)g_B1hi + n0 * 128))[t] = ((float4*)stH)[t];
            ((float4*)((char*)g_B1lo + n0 * 128))[t] = ((float4*)stL)[t];
        }
    } else {
        // W2 image chunk: n in [n0, n0+16). Blocked SW128 atoms, atom_col = k>>6.
        __shared__ __align__(16) char stH[4096];
        __shared__ __align__(16) char stL[4096];
        int n0 = (bx - 9) * 16;
        #pragma unroll
        for (int i = 0; i < 8; i++) {
            int idx = t + 256 * i;          // 0..2047 : k = idx>>4 (128), nl = idx&15
            int k = idx >> 4, nl = idx & 15;
            float wv = W2[k * 128 + n0 + nl];
            __nv_bfloat16 h = __float2bfloat16_rn(wv);
            __nv_bfloat16 l = __float2bfloat16_rn(wv - __bfloat162float(h));
            int ac = k >> 6;
            uint32_t loc = ((uint32_t)(nl >> 3) << 10) | ((uint32_t)(nl & 7) << 7)
                         | ((uint32_t)(k & 63) << 1);
            loc = swz(loc) + (uint32_t)ac * 2048;
            *(__nv_bfloat16*)(stH + loc) = h;
            *(__nv_bfloat16*)(stL + loc) = l;
        }
        __syncthreads();
        {
            int ac = t >> 7, off = t & 127;   // 256 float4 units total
            char* dH = (char*)g_B2hi + ac * 16384 + (n0 >> 3) * 1024;
            char* dL = (char*)g_B2lo + ac * 16384 + (n0 >> 3) * 1024;
            ((float4*)dH)[off] = ((float4*)(stH + ac * 2048))[off];
            ((float4*)dL)[off] = ((float4*)(stL + ac * 2048))[off];
        }
    }
}

// ---------------- main kernel: one symbol, arch-selected body ----------------
__global__ void __launch_bounds__(256, 2)
main_kernel(const float* __restrict__ u,
            const float* __restrict__ W1, const float* __restrict__ b1,
            const float* __restrict__ W2, const float* __restrict__ b2) {
#if TC_OK
    // ================= tcgen05 split-bf16 path, 2 CTAs/SM =================
    extern __shared__ char sb[];
    const int tid = threadIdx.x;
    const int w = tid >> 5;
    const int lane = tid & 31;
    const int tile = blockIdx.x;
    const int b = blockIdx.y;
    uint32_t sb32 = smem_to_u32(sb);

    if (w == 0) TCGEN05_ALLOC(sb32 + S_CTRL, TMEM_COLS);
    if (tid == 0) MBARRIER_INIT(sb32 + S_CTRL + 8, 1);

    // ---- phase 0: u tile -> split-bf16 A1 (SW128 K-major), copy B1 image ----
    {
        int row = tid >> 1, kh = (tid & 1) << 5;
        const float4* up = (const float4*)(u + ((size_t)b * SEQN + (size_t)tile * 128 + row) * 64 + kh);
        #pragma unroll
        for (int i = 0; i < 8; i++) {
            float4 v = up[i];
            __nv_bfloat16 h0 = __float2bfloat16_rn(v.x), h1 = __float2bfloat16_rn(v.y);
            __nv_bfloat16 h2 = __float2bfloat16_rn(v.z), h3 = __float2bfloat16_rn(v.w);
            uint32_t hiA = (uint32_t)__bfloat16_as_ushort(h0) | ((uint32_t)__bfloat16_as_ushort(h1) << 16);
            uint32_t hiB = (uint32_t)__bfloat16_as_ushort(h2) | ((uint32_t)__bfloat16_as_ushort(h3) << 16);
            uint32_t loA = pk_bf(v.x - __bfloat162float(h0), v.y - __bfloat162float(h1));
            uint32_t loB = pk_bf(v.z - __bfloat162float(h2), v.w - __bfloat162float(h3));
            uint32_t sw = swz((uint32_t)(row * 128 + (kh + 4 * i) * 2));
            *(ULL*)(sb + S_A1HI + sw) = (ULL)hiA | ((ULL)hiB << 32);
            *(ULL*)(sb + S_A1LO + sw) = (ULL)loA | ((ULL)loB << 32);
        }
    }
    {
        const float4* gh = (const float4*)g_B1hi;
        const float4* gl = (const float4*)g_B1lo;
        float4* sh = (float4*)(sb + S_B1HI);
        float4* sl = (float4*)(sb + S_B1LO);
        #pragma unroll
        for (int i = 0; i < 4; i++) {
            sh[tid + i * 256] = gh[tid + i * 256];
            sl[tid + i * 256] = gl[tid + i * 256];
        }
    }
    ((float*)(sb + S_AVEC))[tid] = g_a[tid];
    if (tid < 128) {
        ((float*)(sb + S_B1B))[tid] = b1[tid];
        ((float*)(sb + S_B2B))[tid] = b2[tid];
    }
    if (tid < 2) ((float*)(sb + S_CTRL + 16))[tid] = g_c[tid];
    asm volatile("fence.proxy.async.shared::cta;" ::: "memory");
    __syncthreads();

    uint32_t tbase;
    asm volatile("ld.shared.b32 %0, [%1];" : "=r"(tbase) : "r"(sb32 + S_CTRL));

    // ---- GEMM1: D = A1 @ B1^T  (3 split terms x 4 K-chunks, SS mode) ----
    if (w == 0) {
        uint64_t aH = MAKE_SMEM_DESC(sb32 + S_A1HI), aL = MAKE_SMEM_DESC(sb32 + S_A1LO);
        uint64_t bH = MAKE_SMEM_DESC(sb32 + S_B1HI), bL = MAKE_SMEM_DESC(sb32 + S_B1LO);
        if (elect_one_pred()) {
            #pragma unroll
            for (int k = 0; k < 4; k++) mma_f16_ss(tbase + T_D, aH + 2 * k, bH + 2 * k, IDESC, k > 0);
            #pragma unroll
            for (int k = 0; k < 4; k++) mma_f16_ss(tbase + T_D, aH + 2 * k, bL + 2 * k, IDESC, 1);
            #pragma unroll
            for (int k = 0; k < 4; k++) mma_f16_ss(tbase + T_D, aL + 2 * k, bH + 2 * k, IDESC, 1);
            TCGEN05_COMMIT(sb32 + S_CTRL + 8);
        }
    }

    // ---- prefetch B2 image into registers while GEMM1 runs ----
    float4 pf[16];
    {
        const float4* gh = (const float4*)g_B2hi;   // 2048 float4
        const float4* gl = (const float4*)g_B2lo;
        #pragma unroll
        for (int i = 0; i < 8; i++) pf[i] = gh[tid + i * 256];
        #pragma unroll
        for (int i = 0; i < 8; i++) pf[8 + i] = gl[tid + i * 256];
    }

    MBARRIER_WAIT_PARITY(sb32 + S_CTRL + 8, 0);
    TCGEN05_FENCE_AFTER();

    // ---- store B2 into (dead) A1/B1 region ----
    {
        float4* sh = (float4*)(sb + S_B2HI);
        float4* sl = (float4*)(sb + S_B2LO);
        #pragma unroll
        for (int i = 0; i < 8; i++) sh[tid + i * 256] = pf[i];
        #pragma unroll
        for (int i = 0; i < 8; i++) sl[tid + i * 256] = pf[8 + i];
    }
    asm volatile("fence.proxy.async.shared::cta;" ::: "memory");

    // ---- epilogue 1: z1 = gelu(D+b1) -> split bf16 -> TMEM A2 (TS operand) ----
    const int part = w & 3;
    const int cbase = (w >> 2) * 64;
    const int r = part * 32 + lane;
    const uint32_t sttm = ((uint32_t)part) << 21;
    {
        const float* b1s = (const float*)(sb + S_B1B);
        #pragma unroll
        for (int ch = 0; ch < 2; ch++) {
            int c0 = cbase + 32 * ch;
            uint32_t d[32];
            TCGEN05_LD_32X32B_X32(d, tbase + T_D + c0);
            TCGEN05_WAIT_LD();
            uint32_t hi[16], lo[16];
            #pragma unroll
            for (int j = 0; j < 16; j++) {
                float z0 = gelu_f(__uint_as_float(d[2 * j]) + b1s[c0 + 2 * j]);
                float z1 = gelu_f(__uint_as_float(d[2 * j + 1]) + b1s[c0 + 2 * j + 1]);
                __nv_bfloat16 h0 = __float2bfloat16_rn(z0), h1 = __float2bfloat16_rn(z1);
                hi[j] = (uint32_t)__bfloat16_as_ushort(h0) | ((uint32_t)__bfloat16_as_ushort(h1) << 16);
                lo[j] = pk_bf(z0 - __bfloat162float(h0), z1 - __bfloat162float(h1));
            }
            TCGEN05_ST_32X32B_X16(tbase + T_A2HI + (c0 >> 1) + sttm, hi);
            TCGEN05_ST_32X32B_X16(tbase + T_A2LO + (c0 >> 1) + sttm, lo);
        }
        TCGEN05_WAIT_ST();
    }
    TCGEN05_FENCE_BEFORE();
    __syncthreads();   // all LDTM of D1 done; A2 + B2 ready

    // ---- GEMM2: D = A2 @ B2^T  (3 split terms x 8 K-chunks, TS mode) ----
    if (w == 0) {
        TCGEN05_FENCE_AFTER();
        uint64_t bH = MAKE_SMEM_DESC(sb32 + S_B2HI), bL = MAKE_SMEM_DESC(sb32 + S_B2LO);
        if (elect_one_pred()) {
            #pragma unroll
            for (int k = 0; k < 8; k++) {
                uint64_t o = (k < 4) ? (uint64_t)(2 * k) : (uint64_t)(1024 + 2 * (k - 4));
                mma_f16_ts(tbase + T_D, tbase + T_A2HI + 8 * k, bH + o, IDESC, k > 0);
            }
            #pragma unroll
            for (int k = 0; k < 8; k++) {
                uint64_t o = (k < 4) ? (uint64_t)(2 * k) : (uint64_t)(1024 + 2 * (k - 4));
                mma_f16_ts(tbase + T_D, tbase + T_A2HI + 8 * k, bL + o, IDESC, 1);
            }
            #pragma unroll
            for (int k = 0; k < 8; k++) {
                uint64_t o = (k < 4) ? (uint64_t)(2 * k) : (uint64_t)(1024 + 2 * (k - 4));
                mma_f16_ts(tbase + T_D, tbase + T_A2LO + 8 * k, bH + o, IDESC, 1);
            }
            TCGEN05_COMMIT(sb32 + S_CTRL + 8);
        }
    }
    MBARRIER_WAIT_PARITY(sb32 + S_CTRL + 8, 1);
    TCGEN05_FENCE_AFTER();

    // ---- epilogue 2: z2 = gelu(D+b2); score partials; z2 -> smem (stride 129) ----
    {
        float* z2s = (float*)(sb + S_Z2);
        const float* av = (const float*)(sb + S_AVEC);
        const float* b2s = (const float*)(sb + S_B2B);
        float sp0 = 0.f, sp1 = 0.f;
        #pragma unroll
        for (int ch = 0; ch < 2; ch++) {
            int c0 = cbase + 32 * ch;
            uint32_t d[32];
            TCGEN05_LD_32X32B_X32(d, tbase + T_D + c0);
            TCGEN05_WAIT_LD();
            #pragma unroll
            for (int j = 0; j < 32; j++) {
                float z = gelu_f(__uint_as_float(d[j]) + b2s[c0 + j]);
                z2s[r * 129 + c0 + j] = z;
                sp0 = fmaf(av[c0 + j], z, sp0);
                sp1 = fmaf(av[128 + c0 + j], z, sp1);
            }
        }
        float* sSp = (float*)(sb + S_SP);
        sSp[r * 4 + (w >> 2) * 2 + 0] = sp0;
        sSp[r * 4 + (w >> 2) * 2 + 1] = sp1;
    }
    __syncthreads();

    // combine score halves: s[r][h] = c_h + sp[r][0][h] + sp[r][1][h]
    {
        float* sS = (float*)(sb + S_SS);
        const float* sSp = (const float*)(sb + S_SP);
        const float* cs = (const float*)(sb + S_CTRL + 16);
        int r2 = tid >> 1, h = tid & 1;
        sS[r2 * 2 + h] = cs[h] + sSp[r2 * 4 + h] + sSp[r2 * 4 + 2 + h];
    }
    __syncthreads();

    // phase 4: m_h[col] = sum_r s[r][h] * z2[r][col]
    {
        const float* sS = (const float*)(sb + S_SS);
        const float* z2s = (const float*)(sb + S_Z2);
        int h = tid >> 7, col = tid & 127;
        float m = 0.f;
        #pragma unroll 4
        for (int rr = 0; rr < 128; rr++) m = fmaf(sS[rr * 2 + h], z2s[rr * 129 + col], m);
        g_mp[((size_t)(tile * BATCH + b)) * 256 + tid] = m;
        if (tid < 2) {
            float S = 0.f;
            #pragma unroll 4
            for (int rr = 0; rr < 128; rr++) S += sS[rr * 2 + tid];
            g_Sp[(tile * BATCH + b) * 2 + tid] = S;
        }
    }

    __syncthreads();
    if (tid == 0) MBARRIER_INVAL(sb32 + S_CTRL + 8);
    __syncthreads();
    if (w == 0) TCGEN05_DEALLOC(tbase, TMEM_COLS);

#else
    // ================= compact fallback (never runs on sm_103a) =================
    extern __shared__ char sb[];
    float* sZ  = (float*)(sb + S_Z2);     // stride 129
    float* sA  = (float*)(sb + S_AVEC);
    float* sS  = (float*)(sb + S_SS);
    float* sSp = (float*)(sb + S_SP);
    const int tid = threadIdx.x;
    const int tile = blockIdx.x;
    const int b = blockIdx.y;
    const int r = tid >> 1;
    const int half = tid & 1;
    const int cb = half * 64;

    sA[tid] = g_a[tid];

    float ur[64];
    {
        const float4* up = (const float4*)(u + ((size_t)b * SEQN + (size_t)tile * 128 + r) * 64);
        #pragma unroll
        for (int i = 0; i < 16; i++) {
            float4 v = up[i];
            ur[4 * i] = v.x; ur[4 * i + 1] = v.y; ur[4 * i + 2] = v.z; ur[4 * i + 3] = v.w;
        }
    }
    float zr[64];
    #pragma unroll 2
    for (int c = 0; c < 64; c++) {
        float acc = b1[cb + c];
        #pragma unroll 8
        for (int k = 0; k < 64; k++) acc = fmaf(ur[k], W1[k * 128 + cb + c], acc);
        zr[c] = gelu_f(acc);
    }
    for (int c = 0; c < 64; c++) sZ[r * 129 + cb + c] = zr[c];
    __syncthreads();
    #pragma unroll 2
    for (int c = 0; c < 64; c++) {
        float acc = b2[cb + c];
        #pragma unroll 8
        for (int k = 0; k < 128; k++) acc = fmaf(sZ[r * 129 + k], W2[k * 128 + cb + c], acc);
        zr[c] = gelu_f(acc);
    }
    __syncthreads();   // everyone done reading z1
    {
        float sp0 = 0.f, sp1 = 0.f;
        for (int c = 0; c < 64; c++) {
            float z = zr[c];
            sZ[r * 129 + cb + c] = z;
            sp0 = fmaf(sA[cb + c], z, sp0);
            sp1 = fmaf(sA[128 + cb + c], z, sp1);
        }
        sSp[r * 4 + half * 2 + 0] = sp0;
        sSp[r * 4 + half * 2 + 1] = sp1;
    }
    __syncthreads();
    {
        int r2 = tid >> 1, h = tid & 1;
        sS[r2 * 2 + h] = g_c[h] + sSp[r2 * 4 + h] + sSp[r2 * 4 + 2 + h];
    }
    __syncthreads();
    {
        int h = tid >> 7, col = tid & 127;
        float m = 0.f;
        #pragma unroll 4
        for (int rr = 0; rr < 128; rr++) m = fmaf(sS[rr * 2 + h], sZ[rr * 129 + col], m);
        g_mp[((size_t)(tile * BATCH + b)) * 256 + tid] = m;
        if (tid < 2) {
            float S = 0.f;
            #pragma unroll 4
            for (int rr = 0; rr < 128; rr++) S += sS[rr * 2 + tid];
            g_Sp[(tile * BATCH + b) * 2 + tid] = S;
        }
    }
#endif
}

// ---------------- finish: reduce partials, V-proj, O-proj ----------------
__global__ void finish_kernel(const float* __restrict__ Wv, const float* __restrict__ bv,
                              const float* __restrict__ Wo, const float* __restrict__ bo,
                              float* __restrict__ out) {
    __shared__ float sm[256];
    __shared__ float sSs[2];
    __shared__ float sop[128];
    int b = blockIdx.x;
    int t = threadIdx.x;  // 128 threads
    float m0 = 0.f, m1 = 0.f;
    for (int tile = 0; tile < TILES; tile++) {
        const float* p = g_mp + ((size_t)(tile * BATCH + b)) * 256;
        m0 += p[t];
        m1 += p[128 + t];
    }
    sm[t] = m0;
    sm[128 + t] = m1;
    if (t < 2) {
        float S = 0.f;
        for (int tile = 0; tile < TILES; tile++) S += g_Sp[(tile * BATCH + b) * 2 + t];
        sSs[t] = S;
    }
    __syncthreads();
    int h = t >> 6;
    float acc = 0.f;
    #pragma unroll 4
    for (int d = 0; d < 128; d++) acc = fmaf(sm[h * 128 + d], Wv[d * 128 + t], acc);
    acc = (acc + sSs[h] * bv[t]) * (1.0f / (float)SEQN);
    sop[t] = acc;
    __syncthreads();
    float o = bo[t];
    #pragma unroll 4
    for (int j = 0; j < 128; j++) o = fmaf(sop[j], Wo[j * 128 + t], o);
    out[b * 128 + t] = o;
}

// ---------------- launch ----------------
extern "C" void kernel_launch(void* const* d_in, const int* in_sizes, int n_in,
                              void* d_out, int out_size) {
    const float* u     = (const float*)d_in[0];
    // d_in[1] = x, unused by the reference output
    const float* W1    = (const float*)d_in[2];
    const float* b1    = (const float*)d_in[3];
    const float* W2    = (const float*)d_in[4];
    const float* b2    = (const float*)d_in[5];
    const float* embed = (const float*)d_in[6];
    const float* Wq    = (const float*)d_in[7];
    const float* bq    = (const float*)d_in[8];
    const float* Wk    = (const float*)d_in[9];
    const float* bk    = (const float*)d_in[10];
    const float* Wv    = (const float*)d_in[11];
    const float* bv    = (const float*)d_in[12];
    const float* Wo    = (const float*)d_in[13];
    const float* bo    = (const float*)d_in[14];
    float* out = (float*)d_out;

    cudaFuncSetAttribute(main_kernel, cudaFuncAttributeMaxDynamicSharedMemorySize, S_TOTAL);

    prep_kernel<<<17, 256>>>(embed, Wq, bq, Wk, bk, W1, W2);
    main_kernel<<<dim3(TILES, BATCH), 256, S_TOTAL>>>(u, W1, b1, W2, b2);
    finish_kernel<<<BATCH, 128>>>(Wv, bv, Wo, bo, out);
}